// round 4
// baseline (speedup 1.0000x reference)
#include <cuda_runtime.h>
#include <math.h>
#include <stdint.h>

#define NN 50000
#define EE 800000
#define INF_F 128
#define OUTF 64
#define HH 4
#define DD 16

// ---------------- device scratch (no allocations allowed) ----------------
__device__ float g_q[NN * OUTF];
__device__ float g_k[NN * OUTF];
__device__ float g_v[NN * OUTF];
__device__ int   g_cnt[NN];
__device__ int   g_rs[NN];
__device__ int   g_cur[NN];
__device__ int   g_csr[EE];
__device__ int   g_is64;
__device__ int   g_total;

// packed f32x2 FMA: d = a*b + c elementwise on packed pairs (Blackwell FFMA2)
__device__ __forceinline__ unsigned long long ffma2(
    unsigned long long a, unsigned long long b, unsigned long long c)
{
    unsigned long long d;
    asm("fma.rn.f32x2 %0, %1, %2, %3;" : "=l"(d) : "l"(a), "l"(b), "l"(c));
    return d;
}

__device__ __forceinline__ float unpack_sum(unsigned long long a) {
    float lo = __uint_as_float((unsigned)(a & 0xffffffffu));
    float hi = __uint_as_float((unsigned)(a >> 32));
    return lo + hi;
}

// ---------------- prep: zero histogram/total + edge dtype detection -------
// If edge_index is really int32, reading it as int64 packs two indices into one
// word -> out-of-range with overwhelming probability over 1024 words.
__global__ void prep_kernel(const void* ei) {
    int i = blockIdx.x * blockDim.x + threadIdx.x;
    if (i < NN) g_cnt[i] = 0;
    if (i == 0) g_total = 0;
    if (blockIdx.x == 0 && threadIdx.x < 32) {
        int lane = threadIdx.x;
        const long long* e64 = (const long long*)ei;
        int ok = 1;
        for (int t = lane; t < 1024; t += 32) {
            long long v = e64[t];
            if (v < 0 || v >= NN) ok = 0;
        }
        unsigned b = __ballot_sync(0xffffffffu, ok);
        if (lane == 0) g_is64 = (b == 0xffffffffu) ? 1 : 0;
    }
}

// ---------------- fused QKV projection ------------------------------------
// block = 192 threads (thread = one output column among q|k|v), tile = 8 rows.
// Inner product accumulated as packed f32x2 pairs along K (FFMA2, 2x rate).
__global__ __launch_bounds__(192) void qkv_kernel(
    const float* __restrict__ x,
    const float* __restrict__ Wq, const float* __restrict__ bq,
    const float* __restrict__ Wk, const float* __restrict__ bk,
    const float* __restrict__ Wv, const float* __restrict__ bv)
{
    __shared__ __align__(16) float xs[8 * 128];
    int tid = threadIdx.x;
    int sel = tid >> 6;   // 0 -> q, 1 -> k, 2 -> v
    int cc  = tid & 63;

    const float* W;
    const float* bias;
    float* out;
    if (sel == 0)      { W = Wq; bias = bq; out = g_q; }
    else if (sel == 1) { W = Wk; bias = bk; out = g_k; }
    else               { W = Wv; bias = bv; out = g_v; }

    int tile = blockIdx.x;                  // 6250 tiles * 8 rows = 50000 exactly
    const float4* xg4 = (const float4*)(x + (size_t)tile * 8 * 128);
    float4* xs4 = (float4*)xs;
    for (int i = tid; i < 256; i += 192) xs4[i] = xg4[i];
    __syncthreads();

    unsigned long long acc[8];
#pragma unroll
    for (int r = 0; r < 8; r++) acc[r] = 0ull;

    const ulonglong2* Wr = (const ulonglong2*)(W + cc * 128);
    const ulonglong2* xs2 = (const ulonglong2*)xs;
#pragma unroll 4
    for (int k4 = 0; k4 < 32; k4++) {
        ulonglong2 w = Wr[k4];
#pragma unroll
        for (int r = 0; r < 8; r++) {
            ulonglong2 xv = xs2[r * 32 + k4];
            acc[r] = ffma2(w.x, xv.x, acc[r]);
            acc[r] = ffma2(w.y, xv.y, acc[r]);
        }
    }

    float b = bias[cc];
    int row0 = tile * 8;
#pragma unroll
    for (int r = 0; r < 8; r++) out[(row0 + r) * 64 + cc] = unpack_sum(acc[r]) + b;
}

// ---------------- CSR build ----------------
// histogram: 2 edges per thread, vectorized index loads
__global__ void hist_kernel(const void* ei) {
    int is64 = g_is64;
    int t = blockIdx.x * blockDim.x + threadIdx.x;
    if (t >= EE / 2) return;
    int d0, d1;
    if (is64) {
        longlong2 d = ((const longlong2*)((const long long*)ei + EE))[t];
        d0 = (int)d.x; d1 = (int)d.y;
    } else {
        int2 d = ((const int2*)((const int*)ei + EE))[t];
        d0 = d.x; d1 = d.y;
    }
    atomicAdd(&g_cnt[d0], 1);
    atomicAdd(&g_cnt[d1], 1);
}

// range allocation: order-free replacement for a prefix scan. Each node gets
// a contiguous chunk [off, off+cnt) via one aggregated atomic (REDUX.SUM).
__global__ void alloc_kernel() {
    int i = blockIdx.x * blockDim.x + threadIdx.x;
    if (i >= NN) return;
    int c = g_cnt[i];
    int off = atomicAdd(&g_total, c);
    g_rs[i] = off;
    g_cur[i] = off;
}

// scatter: 2 edges per thread, vectorized index loads
__global__ void scatter_kernel(const void* ei) {
    int is64 = g_is64;
    int t = blockIdx.x * blockDim.x + threadIdx.x;
    if (t >= EE / 2) return;
    int s0, s1, d0, d1;
    if (is64) {
        const long long* e = (const long long*)ei;
        longlong2 sv = ((const longlong2*)e)[t];
        longlong2 dv = ((const longlong2*)(e + EE))[t];
        s0 = (int)sv.x; s1 = (int)sv.y;
        d0 = (int)dv.x; d1 = (int)dv.y;
    } else {
        const int* e = (const int*)ei;
        int2 sv = ((const int2*)e)[t];
        int2 dv = ((const int2*)(e + EE))[t];
        s0 = sv.x; s1 = sv.y;
        d0 = dv.x; d1 = dv.y;
    }
    g_csr[atomicAdd(&g_cur[d0], 1)] = s0;
    g_csr[atomicAdd(&g_cur[d1], 1)] = s1;
}

// ---------------- fused gather attention + output projection ----------------
// One warp per dst node. lane l owns flat dims {2l, 2l+1}; head h = l/8; 8-lane
// groups reduce Minkowski dots via shfl. <q,q> computed inline from the loaded
// q row (no gather); <k,k> once per node in the prologue.
// exp(-acosh(arg)) == 1/(arg + sqrt(arg^2-1))  -> no MUFU log/exp.
// Softmax denom cancels exactly into the L2 norm: att = S / (||S|| + EPS*s).
// Epilogue: out = att @ Wo^T + bo computed in-warp via smem staging (Wo is
// L1-resident, 16KB).
__global__ __launch_bounds__(256) void attn_out_kernel(
    const float* __restrict__ Wo, const float* __restrict__ bo,
    float* __restrict__ outp)
{
    __shared__ __align__(16) float satt[8][64];
    int gtid = blockIdx.x * blockDim.x + threadIdx.x;
    int i = gtid >> 5;
    if (i >= NN) return;
    int w = threadIdx.x >> 5;
    int lane = threadIdx.x & 31;
    int dp = lane & 7;

    float2 kv = *(const float2*)(g_k + i * 64 + 2 * lane);
    float sign = (dp == 7) ? -1.f : 1.f;   // flat dim 15 carries Minkowski minus

    // <k,k> per head from registers
    float kkv = fmaf(kv.x, kv.x, sign * kv.y * kv.y);
    kkv += __shfl_xor_sync(0xffffffffu, kkv, 1);
    kkv += __shfl_xor_sync(0xffffffffu, kkv, 2);
    kkv += __shfl_xor_sync(0xffffffffu, kkv, 4);

    int js = g_rs[i];
    int je = js + g_cnt[i];

    float s = 0.f, a0 = 0.f, a1 = 0.f;
    const float CLMP = (1.0f + 1e-6f) * (1.0f + 1e-6f);

    int j = js;
    for (; j + 3 < je; j += 4) {
        int s0 = g_csr[j];
        int s1 = g_csr[j + 1];
        int s2 = g_csr[j + 2];
        int s3 = g_csr[j + 3];
        float2 q0 = *(const float2*)(g_q + s0 * 64 + 2 * lane);
        float2 q1 = *(const float2*)(g_q + s1 * 64 + 2 * lane);
        float2 q2 = *(const float2*)(g_q + s2 * 64 + 2 * lane);
        float2 q3 = *(const float2*)(g_q + s3 * 64 + 2 * lane);
        float2 v0 = *(const float2*)(g_v + s0 * 64 + 2 * lane);
        float2 v1 = *(const float2*)(g_v + s1 * 64 + 2 * lane);
        float2 v2 = *(const float2*)(g_v + s2 * 64 + 2 * lane);
        float2 v3 = *(const float2*)(g_v + s3 * 64 + 2 * lane);

        float d0 = fmaf(q0.x, kv.x, sign * q0.y * kv.y);
        float d1 = fmaf(q1.x, kv.x, sign * q1.y * kv.y);
        float d2 = fmaf(q2.x, kv.x, sign * q2.y * kv.y);
        float d3 = fmaf(q3.x, kv.x, sign * q3.y * kv.y);
        float e0 = fmaf(q0.x, q0.x, sign * q0.y * q0.y);
        float e1 = fmaf(q1.x, q1.x, sign * q1.y * q1.y);
        float e2 = fmaf(q2.x, q2.x, sign * q2.y * q2.y);
        float e3 = fmaf(q3.x, q3.x, sign * q3.y * q3.y);
#pragma unroll
        for (int o = 1; o <= 4; o <<= 1) {
            d0 += __shfl_xor_sync(0xffffffffu, d0, o);
            d1 += __shfl_xor_sync(0xffffffffu, d1, o);
            d2 += __shfl_xor_sync(0xffffffffu, d2, o);
            d3 += __shfl_xor_sync(0xffffffffu, d3, o);
            e0 += __shfl_xor_sync(0xffffffffu, e0, o);
            e1 += __shfl_xor_sync(0xffffffffu, e1, o);
            e2 += __shfl_xor_sync(0xffffffffu, e2, o);
            e3 += __shfl_xor_sync(0xffffffffu, e3, o);
        }

        float r0 = __fdividef(d0 * d0, fmaxf(fabsf(e0 * kkv), 1e-9f)) + 1e-9f;
        float r1 = __fdividef(d1 * d1, fmaxf(fabsf(e1 * kkv), 1e-9f)) + 1e-9f;
        float r2 = __fdividef(d2 * d2, fmaxf(fabsf(e2 * kkv), 1e-9f)) + 1e-9f;
        float r3 = __fdividef(d3 * d3, fmaxf(fabsf(e3 * kkv), 1e-9f)) + 1e-9f;
        r0 = fmaxf(r0, CLMP);
        r1 = fmaxf(r1, CLMP);
        r2 = fmaxf(r2, CLMP);
        r3 = fmaxf(r3, CLMP);
        float p0 = __frcp_rn(sqrtf(r0) + sqrtf(r0 - 1.0f));
        float p1 = __frcp_rn(sqrtf(r1) + sqrtf(r1 - 1.0f));
        float p2 = __frcp_rn(sqrtf(r2) + sqrtf(r2 - 1.0f));
        float p3 = __frcp_rn(sqrtf(r3) + sqrtf(r3 - 1.0f));

        s += (p0 + p1) + (p2 + p3);
        a0 = fmaf(p0, v0.x, fmaf(p1, v1.x, fmaf(p2, v2.x, fmaf(p3, v3.x, a0))));
        a1 = fmaf(p0, v0.y, fmaf(p1, v1.y, fmaf(p2, v2.y, fmaf(p3, v3.y, a1))));
    }
    for (; j < je; j++) {
        int s0 = g_csr[j];
        float2 q0 = *(const float2*)(g_q + s0 * 64 + 2 * lane);
        float2 v0 = *(const float2*)(g_v + s0 * 64 + 2 * lane);
        float d0 = fmaf(q0.x, kv.x, sign * q0.y * kv.y);
        float e0 = fmaf(q0.x, q0.x, sign * q0.y * q0.y);
#pragma unroll
        for (int o = 1; o <= 4; o <<= 1) {
            d0 += __shfl_xor_sync(0xffffffffu, d0, o);
            e0 += __shfl_xor_sync(0xffffffffu, e0, o);
        }
        float r0 = __fdividef(d0 * d0, fmaxf(fabsf(e0 * kkv), 1e-9f)) + 1e-9f;
        r0 = fmaxf(r0, CLMP);
        float p0 = __frcp_rn(sqrtf(r0) + sqrtf(r0 - 1.0f));
        s += p0;
        a0 = fmaf(p0, v0.x, a0);
        a1 = fmaf(p0, v0.y, a1);
    }

    float nsq = fmaf(a0, a0, a1 * a1);
    nsq += __shfl_xor_sync(0xffffffffu, nsq, 1);
    nsq += __shfl_xor_sync(0xffffffffu, nsq, 2);
    nsq += __shfl_xor_sync(0xffffffffu, nsq, 4);
    float norm = sqrtf(nsq);
    // agg = S/s, attended = agg/(||agg||+EPS) = S/(||S|| + EPS*s); 0 if no mass
    float scale = (norm > 0.f) ? __frcp_rn(norm + 1e-9f * s) : 0.f;
    satt[w][2 * lane]     = a0 * scale;
    satt[w][2 * lane + 1] = a1 * scale;
    __syncwarp();

    // out[i, :] = attended @ Wo^T + bo ; lane handles cols 2*lane, 2*lane+1
    int c0 = 2 * lane;
    unsigned long long acc0 = 0ull, acc1 = 0ull;
    const ulonglong2* a2  = (const ulonglong2*)satt[w];
    const ulonglong2* w02 = (const ulonglong2*)(Wo + c0 * 64);
    const ulonglong2* w12 = (const ulonglong2*)(Wo + (c0 + 1) * 64);
#pragma unroll
    for (int t = 0; t < 16; t++) {
        ulonglong2 a = a2[t];
        ulonglong2 x = w02[t];
        ulonglong2 y = w12[t];
        acc0 = ffma2(a.x, x.x, acc0);
        acc0 = ffma2(a.y, x.y, acc0);
        acc1 = ffma2(a.x, y.x, acc1);
        acc1 = ffma2(a.y, y.y, acc1);
    }
    float2 bv2 = *(const float2*)(bo + c0);
    float2 res;
    res.x = unpack_sum(acc0) + bv2.x;
    res.y = unpack_sum(acc1) + bv2.y;
    *(float2*)(outp + i * 64 + c0) = res;
}

// ---------------- launch: fork-join graph (CSR chain || QKV) -----------------
extern "C" void kernel_launch(void* const* d_in, const int* in_sizes, int n_in,
                              void* d_out, int out_size) {
    const float* x  = (const float*)d_in[0];
    const void*  ei = d_in[1];
    const float* Wq = (const float*)d_in[2];
    const float* bq = (const float*)d_in[3];
    const float* Wk = (const float*)d_in[4];
    const float* bk = (const float*)d_in[5];
    const float* Wv = (const float*)d_in[6];
    const float* bv = (const float*)d_in[7];
    const float* Wo = (const float*)d_in[8];
    const float* bo = (const float*)d_in[9];
    float* out = (float*)d_out;

    cudaStream_t s2;
    cudaStreamCreateWithFlags(&s2, cudaStreamNonBlocking);
    cudaEvent_t eF, eJ;
    cudaEventCreateWithFlags(&eF, cudaEventDisableTiming);
    cudaEventCreateWithFlags(&eJ, cudaEventDisableTiming);

    // fork: qkv runs on s2 in parallel with the CSR chain on the main stream
    cudaEventRecord(eF, 0);
    cudaStreamWaitEvent(s2, eF, 0);
    qkv_kernel<<<NN / 8, 192, 0, s2>>>(x, Wq, bq, Wk, bk, Wv, bv);
    cudaEventRecord(eJ, s2);

    prep_kernel<<<(NN + 255) / 256, 256>>>(ei);
    hist_kernel<<<(EE / 2 + 255) / 256, 256>>>(ei);
    alloc_kernel<<<(NN + 255) / 256, 256>>>();
    scatter_kernel<<<(EE / 2 + 255) / 256, 256>>>(ei);

    // join
    cudaStreamWaitEvent(0, eJ, 0);
    attn_out_kernel<<<(NN * 32) / 256, 256>>>(Wo, bo, out);
}